// round 2
// baseline (speedup 1.0000x reference)
#include <cuda_runtime.h>
#include <cstdint>
#include <cstddef>

#define BATCH 32
#define SEQT  2048
#define INSZ  512
#define HID   512
#define G3    1536
#define NB    128        // persistent CTAs for the scan (<= 148 SMs -> co-resident)
#define NT    256

// ---- device scratch (static allocs are the sanctioned no-cudaMalloc path) ----
__device__ float g_xg[(size_t)SEQT * BATCH * G3];   // [t][b][3H], ~402 MB BSS
__device__ float g_h[2][BATCH * HID];               // double-buffered hidden state
__device__ unsigned g_bar_count;                    // grid barrier (ends at 0 each launch)
__device__ unsigned g_bar_gen;                      // monotonic generation

// =============================================================
// Kernel A: x_gates = input @ W_ih^T + b_ih   (fp32 SGEMM 128x128x8)
// =============================================================
__global__ __launch_bounds__(256) void gemm_xgates(
    const float* __restrict__ A,      // [B*T, 512] row-major (b major, t minor)
    const float* __restrict__ Wih,    // [1536, 512]
    const float* __restrict__ bih) {  // [1536]
  __shared__ float As[8][128];
  __shared__ float Bs[8][128];
  const int tid = threadIdx.x;
  const int m0 = blockIdx.y << 7;
  const int n0 = blockIdx.x << 7;
  const int tx = tid & 15, ty = tid >> 4;
  const int lr = tid >> 1;
  const int lc = (tid & 1) << 2;

  float acc[8][8];
#pragma unroll
  for (int i = 0; i < 8; i++)
#pragma unroll
    for (int j = 0; j < 8; j++) acc[i][j] = 0.f;

  const float* Ap = A + (size_t)(m0 + lr) * INSZ + lc;
  const float* Bp = Wih + (size_t)(n0 + lr) * INSZ + lc;

  for (int k0 = 0; k0 < INSZ; k0 += 8) {
    float4 av = *(const float4*)(Ap + k0);
    float4 bv = *(const float4*)(Bp + k0);
    As[lc + 0][lr] = av.x; As[lc + 1][lr] = av.y;
    As[lc + 2][lr] = av.z; As[lc + 3][lr] = av.w;
    Bs[lc + 0][lr] = bv.x; Bs[lc + 1][lr] = bv.y;
    Bs[lc + 2][lr] = bv.z; Bs[lc + 3][lr] = bv.w;
    __syncthreads();
#pragma unroll
    for (int k = 0; k < 8; k++) {
      float af[8], bf[8];
      *(float4*)(af)     = *(const float4*)&As[k][ty * 8];
      *(float4*)(af + 4) = *(const float4*)&As[k][ty * 8 + 4];
      *(float4*)(bf)     = *(const float4*)&Bs[k][tx * 8];
      *(float4*)(bf + 4) = *(const float4*)&Bs[k][tx * 8 + 4];
#pragma unroll
      for (int i = 0; i < 8; i++)
#pragma unroll
        for (int j = 0; j < 8; j++) acc[i][j] += af[i] * bf[j];
    }
    __syncthreads();
  }

  float bb_[8];
  *(float4*)(bb_)     = *(const float4*)(bih + n0 + tx * 8);
  *(float4*)(bb_ + 4) = *(const float4*)(bih + n0 + tx * 8 + 4);
#pragma unroll
  for (int i = 0; i < 8; i++) {
    int m = m0 + ty * 8 + i;
    int b = m >> 11;        // / 2048
    int t = m & 2047;       // % 2048
    float* orow = g_xg + ((size_t)t * BATCH + b) * G3 + n0 + tx * 8;
    float4 o0, o1;
    o0.x = acc[i][0] + bb_[0]; o0.y = acc[i][1] + bb_[1];
    o0.z = acc[i][2] + bb_[2]; o0.w = acc[i][3] + bb_[3];
    o1.x = acc[i][4] + bb_[4]; o1.y = acc[i][5] + bb_[5];
    o1.z = acc[i][6] + bb_[6]; o1.w = acc[i][7] + bb_[7];
    *(float4*)(orow)     = o0;
    *(float4*)(orow + 4) = o1;
  }
}

// =============================================================
// Kernel B: persistent GRU scan with software grid barrier
// =============================================================
__device__ __forceinline__ void grid_barrier() {
  __syncthreads();
  if (threadIdx.x == 0) {
    __threadfence();  // release all prior global writes
    unsigned gen = *(volatile unsigned*)&g_bar_gen;  // read BEFORE arriving
    unsigned a = atomicAdd(&g_bar_count, 1u);
    if (a == (unsigned)(gridDim.x - 1)) {
      g_bar_count = 0;               // sole writer at this point
      __threadfence();
      atomicAdd(&g_bar_gen, 1u);     // release next phase
    } else {
      while (*(volatile unsigned*)&g_bar_gen == gen) { }
    }
    __threadfence();  // acquire
  }
  __syncthreads();
}

__device__ __forceinline__ float sigmoid_f(float x) {
  return 1.f / (1.f + __expf(-x));
}
__device__ __forceinline__ float tanh_f(float x) {
  float e = __expf(-2.f * x);
  return (1.f - e) / (1.f + e);
}

// dynamic shared layout (floats):
//   ws  [12 * 512]   = 6144    W_hh slice, row r = jj*3 + g  -> global row g*512 + j0 + jj
//   hs  [32 * 512]   = 16384   staged previous h
//   red [8 * 48]     = 384     per-warp reduced dot products
//   bh  [16]                   bias_hh slice
#define SMEM_FLOATS (6144 + 16384 + 384 + 16)

__global__ __launch_bounds__(NT, 1) void gru_scan(
    const float* __restrict__ Whh,   // [1536, 512]
    const float* __restrict__ bhh,   // [1536]
    const float* __restrict__ h0,    // [1, 32, 512]
    float* __restrict__ out) {       // [32, 2048, 512]
  extern __shared__ float smem[];
  float* ws  = smem;
  float* hs  = smem + 6144;
  float* red = hs + 16384;
  float* bh  = red + 384;

  const int tid  = threadIdx.x;
  const int j0   = blockIdx.x << 2;           // 4 hidden units per CTA
  const int w    = tid >> 5;
  const int lane = tid & 31;
  const int bg   = w >> 1;                    // batch group (8 batches)
  const int rg   = w & 1;                     // row group (6 of 12 rows)
  const int b0   = bg << 3;

  // --- load W_hh slice into shared (row-major [12][512]) ---
  for (int idx = tid; idx < 12 * (INSZ / 4); idx += NT) {
    int r  = idx >> 7;          // 0..11
    int kc = idx & 127;
    int jj = r / 3;
    int g  = r - jj * 3;
    float4 v = *(const float4*)(Whh + (size_t)(g * HID + j0 + jj) * HID + (kc << 2));
    *(float4*)&ws[r * INSZ + (kc << 2)] = v;
  }
  if (tid < 12) {
    int jj = tid / 3, g = tid - jj * 3;
    bh[tid] = bhh[g * HID + j0 + jj];
  }
  // --- copy h0 slice into g_h[0] ---
  for (int idx = tid; idx < BATCH * 4; idx += NT) {
    int b = idx >> 2, jj = idx & 3;
    g_h[0][b * HID + j0 + jj] = h0[b * HID + j0 + jj];
  }
  grid_barrier();  // full h0 visible everywhere

  const float* wsr = ws + (rg * 6) * INSZ;

  for (int t = 0; t < SEQT; t++) {
    const float* hp = g_h[t & 1];
    float* hn = g_h[(t + 1) & 1];

    // --- stage previous h (64 KB) into shared, bypassing stale L1 ---
    {
      const float4* hp4 = (const float4*)hp;
      float4* hs4 = (float4*)hs;
#pragma unroll
      for (int i = 0; i < 16; i++) {
        int idx = i * NT + tid;   // 4096 float4 total
        hs4[idx] = __ldcg(hp4 + idx);
      }
    }
    __syncthreads();

    // --- per-warp 8b x 6r register tile, k split across 32 lanes ---
    float acc[48];
#pragma unroll
    for (int c = 0; c < 48; c++) acc[c] = 0.f;

    const float* hsb = hs + b0 * HID;
#pragma unroll
    for (int i4 = 0; i4 < 4; i4++) {
      int k = i4 * 128 + (lane << 2);
      float4 wv[6], hv[8];
#pragma unroll
      for (int rr = 0; rr < 6; rr++)
        wv[rr] = *(const float4*)(wsr + rr * INSZ + k);
#pragma unroll
      for (int bb = 0; bb < 8; bb++)
        hv[bb] = *(const float4*)(hsb + bb * HID + k);
#pragma unroll
      for (int rr = 0; rr < 6; rr++)
#pragma unroll
        for (int bb = 0; bb < 8; bb++) {
          float s = acc[rr * 8 + bb];
          s += wv[rr].x * hv[bb].x;
          s += wv[rr].y * hv[bb].y;
          s += wv[rr].z * hv[bb].z;
          s += wv[rr].w * hv[bb].w;
          acc[rr * 8 + bb] = s;
        }
    }

    // --- butterfly reduce over lanes; scatter 48 sums to shared ---
#pragma unroll
    for (int rr = 0; rr < 6; rr++)
#pragma unroll
      for (int bb = 0; bb < 8; bb++) {
        float v = acc[rr * 8 + bb];
        v += __shfl_xor_sync(0xffffffffu, v, 16);
        v += __shfl_xor_sync(0xffffffffu, v, 8);
        v += __shfl_xor_sync(0xffffffffu, v, 4);
        v += __shfl_xor_sync(0xffffffffu, v, 2);
        v += __shfl_xor_sync(0xffffffffu, v, 1);
        const int c = rr * 8 + bb;
        if (lane == (c & 31)) red[w * 48 + c] = v;
      }
    __syncwarp();

    // --- gate math + state update: 16 lanes/warp, one (b, j) each ---
    if (lane < 16) {
      int bb  = lane >> 1;
      int jj2 = lane & 1;
      int b   = b0 + bb;
      int j   = j0 + (rg << 1) + jj2;
      float sr = red[w * 48 + (jj2 * 3 + 0) * 8 + bb];
      float sz = red[w * 48 + (jj2 * 3 + 1) * 8 + bb];
      float sn = red[w * 48 + (jj2 * 3 + 2) * 8 + bb];
      int rbase = rg * 6 + jj2 * 3;
      const float* xgp = g_xg + ((size_t)t * BATCH + b) * G3;
      float xr = xgp[j];
      float xz = xgp[HID + j];
      float xn = xgp[2 * HID + j];
      float rgate = sigmoid_f(xr + sr + bh[rbase + 0]);
      float zgate = sigmoid_f(xz + sz + bh[rbase + 1]);
      float hn_pre = sn + bh[rbase + 2];
      float ngate = tanh_f(xn + rgate * hn_pre);
      float hprev = hs[b * HID + j];
      float hnew = ngate + zgate * (hprev - ngate);
      hn[b * HID + j] = hnew;
      out[((size_t)b * SEQT + t) * HID + j] = hnew;
    }

    grid_barrier();  // h_t complete & visible before anyone stages step t+1
  }
}

// =============================================================
extern "C" void kernel_launch(void* const* d_in, const int* in_sizes, int n_in,
                              void* d_out, int out_size) {
  (void)in_sizes; (void)n_in; (void)out_size;
  const float* input = (const float*)d_in[0];  // [32, 2048, 512]
  const float* h0    = (const float*)d_in[1];  // [1, 32, 512]
  const float* wih   = (const float*)d_in[2];  // [1536, 512]
  const float* whh   = (const float*)d_in[3];  // [1536, 512]
  const float* bih   = (const float*)d_in[4];  // [1536]
  const float* bhh   = (const float*)d_in[5];  // [1536]
  float* out = (float*)d_out;                  // [32, 2048, 512]

  cudaFuncSetAttribute(gru_scan, cudaFuncAttributeMaxDynamicSharedMemorySize,
                       SMEM_FLOATS * (int)sizeof(float));

  dim3 gA(G3 / 128, (BATCH * SEQT) / 128);     // 12 x 512 blocks
  gemm_xgates<<<gA, 256>>>(input, wih, bih);
  gru_scan<<<NB, NT, SMEM_FLOATS * sizeof(float)>>>(whh, bhh, h0, out);
}

// round 3
// speedup vs baseline: 1.4447x; 1.4447x over previous
#include <cuda_runtime.h>
#include <cstdint>
#include <cstddef>

#define BATCH 32
#define SEQT  2048
#define INSZ  512
#define HID   512
#define G3    1536
#define NB    128
#define NT    256
typedef unsigned long long ull;

__device__ float g_xg[(size_t)SEQT * BATCH * G3];   // [t][b][3H]
__device__ float g_h[2][BATCH * HID];
__device__ unsigned g_bar_count;
__device__ unsigned g_bar_gen;

// ---- packed f32x2 helpers ----
__device__ __forceinline__ ull pk2(float x, float y) {
  ull r; asm("mov.b64 %0, {%1,%2};" : "=l"(r) : "f"(x), "f"(y)); return r;
}
__device__ __forceinline__ ull ffma2(ull a, ull b, ull c) {
  ull d; asm("fma.rn.f32x2 %0, %1, %2, %3;" : "=l"(d) : "l"(a), "l"(b), "l"(c)); return d;
}
__device__ __forceinline__ float2 upk2(ull v) {
  float x, y; asm("mov.b64 {%0,%1}, %2;" : "=f"(x), "=f"(y) : "l"(v));
  return make_float2(x, y);
}
__device__ __forceinline__ void ldcg2(const float* p, ull& a, ull& b) {
  asm volatile("ld.global.cg.v2.u64 {%0,%1}, [%2];" : "=l"(a), "=l"(b) : "l"(p));
}

__device__ __forceinline__ float sigmoid_f(float x) { return 1.f / (1.f + __expf(-x)); }
__device__ __forceinline__ float tanh_f(float x) {
  float e = __expf(-2.f * x); return (1.f - e) / (1.f + e);
}

// =============================================================
// Kernel A: x_gates = input @ W_ih^T + b_ih  (FFMA2, BK=16, pipelined)
// =============================================================
__global__ __launch_bounds__(256, 2) void gemm_xgates(
    const float* __restrict__ A, const float* __restrict__ Wih,
    const float* __restrict__ bih) {
  __shared__ float As[16][128];
  __shared__ float Bs[16][128];
  const int tid = threadIdx.x;
  const int m0 = blockIdx.y << 7, n0 = blockIdx.x << 7;
  const int tx = tid & 15, ty = tid >> 4;
  const int lrow = tid & 127, lk = (tid >> 7) * 8;

  const float* Ap = A + (size_t)(m0 + lrow) * INSZ + lk;
  const float* Bp = Wih + (size_t)(n0 + lrow) * INSZ + lk;

  ull acc[4][8];
#pragma unroll
  for (int i = 0; i < 4; i++)
#pragma unroll
    for (int j = 0; j < 8; j++) acc[i][j] = 0ull;

  float4 la0 = *(const float4*)(Ap),     la1 = *(const float4*)(Ap + 4);
  float4 lb0 = *(const float4*)(Bp),     lb1 = *(const float4*)(Bp + 4);

  for (int kt = 0; kt < 32; kt++) {
    __syncthreads();
    As[lk + 0][lrow] = la0.x; As[lk + 1][lrow] = la0.y;
    As[lk + 2][lrow] = la0.z; As[lk + 3][lrow] = la0.w;
    As[lk + 4][lrow] = la1.x; As[lk + 5][lrow] = la1.y;
    As[lk + 6][lrow] = la1.z; As[lk + 7][lrow] = la1.w;
    Bs[lk + 0][lrow] = lb0.x; Bs[lk + 1][lrow] = lb0.y;
    Bs[lk + 2][lrow] = lb0.z; Bs[lk + 3][lrow] = lb0.w;
    Bs[lk + 4][lrow] = lb1.x; Bs[lk + 5][lrow] = lb1.y;
    Bs[lk + 6][lrow] = lb1.z; Bs[lk + 7][lrow] = lb1.w;
    __syncthreads();
    if (kt < 31) {
      Ap += 16; Bp += 16;
      la0 = *(const float4*)(Ap); la1 = *(const float4*)(Ap + 4);
      lb0 = *(const float4*)(Bp); lb1 = *(const float4*)(Bp + 4);
    }
#pragma unroll
    for (int k = 0; k < 16; k++) {
      // a: row pairs (split 4+4), natural packed pairs from transposed smem
      ulonglong2 aA = *(const ulonglong2*)&As[k][ty * 4];
      ulonglong2 aB = *(const ulonglong2*)&As[k][64 + ty * 4];
      ull a2[4] = {aA.x, aA.y, aB.x, aB.y};
      float4 bfa = *(const float4*)&Bs[k][tx * 4];
      float4 bfb = *(const float4*)&Bs[k][64 + tx * 4];
      ull bd[8];
      bd[0] = pk2(bfa.x, bfa.x); bd[1] = pk2(bfa.y, bfa.y);
      bd[2] = pk2(bfa.z, bfa.z); bd[3] = pk2(bfa.w, bfa.w);
      bd[4] = pk2(bfb.x, bfb.x); bd[5] = pk2(bfb.y, bfb.y);
      bd[6] = pk2(bfb.z, bfb.z); bd[7] = pk2(bfb.w, bfb.w);
#pragma unroll
      for (int i = 0; i < 4; i++)
#pragma unroll
        for (int j = 0; j < 8; j++) acc[i][j] = ffma2(a2[i], bd[j], acc[i][j]);
    }
  }

  float4 bb0 = *(const float4*)(bih + n0 + tx * 4);
  float4 bb1 = *(const float4*)(bih + n0 + 64 + tx * 4);
  const float* bbp0 = &bb0.x; const float* bbp1 = &bb1.x;
#pragma unroll
  for (int i = 0; i < 8; i++) {
    int i2 = (i < 4) ? (i >> 1) : (2 + ((i - 4) >> 1));
    int half = i & 1;
    int m = m0 + ((i < 4) ? (ty * 4 + i) : (64 + ty * 4 + i - 4));
    int b = m >> 11, t = m & 2047;
    float* orow = g_xg + ((size_t)t * BATCH + b) * G3 + n0;
    float4 o0, o1;
    float2 p;
    p = upk2(acc[i2][0]); o0.x = (half ? p.y : p.x) + bbp0[0];
    p = upk2(acc[i2][1]); o0.y = (half ? p.y : p.x) + bbp0[1];
    p = upk2(acc[i2][2]); o0.z = (half ? p.y : p.x) + bbp0[2];
    p = upk2(acc[i2][3]); o0.w = (half ? p.y : p.x) + bbp0[3];
    p = upk2(acc[i2][4]); o1.x = (half ? p.y : p.x) + bbp1[0];
    p = upk2(acc[i2][5]); o1.y = (half ? p.y : p.x) + bbp1[1];
    p = upk2(acc[i2][6]); o1.z = (half ? p.y : p.x) + bbp1[2];
    p = upk2(acc[i2][7]); o1.w = (half ? p.y : p.x) + bbp1[3];
    *(float4*)(orow + tx * 4) = o0;
    *(float4*)(orow + 64 + tx * 4) = o1;
  }
}

// =============================================================
// Kernel B: persistent GRU scan (FFMA2, direct-L2 h reads, 24-SHFL reduce)
// =============================================================
__device__ __forceinline__ void grid_barrier() {
  __syncthreads();
  if (threadIdx.x == 0) {
    __threadfence();
    unsigned gen = *(volatile unsigned*)&g_bar_gen;
    unsigned a = atomicAdd(&g_bar_count, 1u);
    if (a == (unsigned)(gridDim.x - 1)) {
      g_bar_count = 0;
      __threadfence();
      atomicAdd(&g_bar_gen, 1u);
    } else {
      while (*(volatile unsigned*)&g_bar_gen == gen) { }
    }
    __threadfence();
  }
  __syncthreads();
}

__global__ __launch_bounds__(NT, 1) void gru_scan(
    const float* __restrict__ Whh, const float* __restrict__ bhh,
    const float* __restrict__ h0, float* __restrict__ out) {
  __shared__ float ws[12 * HID];     // row r=jj*3+g  <-> Whh row g*512+j0+jj
  __shared__ float red[8 * 8 * 12];  // [warp][bb][12]
  __shared__ float bh[12];

  const int tid = threadIdx.x;
  const int j0 = blockIdx.x << 2;
  const int w = tid >> 5, lane = tid & 31;
  const int bg = w >> 1, kh = w & 1;
  const int bb = lane >> 2, kq = lane & 3;
  const int b0 = bg << 3;
  const int kbase = kh * 256;

  for (int idx = tid; idx < 12 * (HID / 4); idx += NT) {
    int r = idx >> 7, kc = idx & 127;
    int jj = r / 3, g = r - jj * 3;
    *(float4*)&ws[r * HID + (kc << 2)] =
        *(const float4*)(Whh + (size_t)(g * HID + j0 + jj) * HID + (kc << 2));
  }
  if (tid < 12) { int jj = tid / 3, g = tid - jj * 3; bh[tid] = bhh[g * HID + j0 + jj]; }
  if (tid < 128) {
    int b = tid >> 2, jj = tid & 3;
    g_h[0][b * HID + j0 + jj] = h0[b * HID + j0 + jj];
  }
  grid_barrier();

  const int b_ = tid >> 2, jj_ = tid & 3, jcol = j0 + jj_;

  for (int t = 0; t < SEQT; t++) {
    const float* hp = g_h[t & 1];
    float* hn = g_h[(t + 1) & 1];

    // prefetch per-output operands (threads 0..127)
    float xr = 0.f, xz = 0.f, xn = 0.f, hprev = 0.f;
    if (tid < 128) {
      const float* xgp = g_xg + ((size_t)t * BATCH + b_) * G3 + jcol;
      xr = __ldcg(xgp); xz = __ldcg(xgp + HID); xn = __ldcg(xgp + 2 * HID);
      hprev = __ldcg(hp + b_ * HID + jcol);
    }

    // h reads: each lane 16x LDG.128 from L2 (each element read once per CTA)
    const float* hrow = hp + (b0 + bb) * HID + kbase + (kq << 2);
    ull hx[16], hy[16];
#pragma unroll
    for (int s = 0; s < 16; s++) ldcg2(hrow + s * 16, hx[s], hy[s]);

    ull acc[12];
#pragma unroll
    for (int r = 0; r < 12; r++) acc[r] = 0ull;
#pragma unroll
    for (int s = 0; s < 16; s++) {
      const float* wk = ws + kbase + s * 16 + (kq << 2);
#pragma unroll
      for (int r = 0; r < 12; r++) {
        ulonglong2 w2 = *(const ulonglong2*)(wk + r * HID);
        acc[r] = ffma2(w2.x, hx[s], acc[r]);
        acc[r] = ffma2(w2.y, hy[s], acc[r]);
      }
    }

    // reduce over kq (2 shuffles per value), stash per-(warp,bb)
#pragma unroll
    for (int r = 0; r < 12; r++) {
      float2 p = upk2(acc[r]);
      float v = p.x + p.y;
      v += __shfl_xor_sync(0xffffffffu, v, 1);
      v += __shfl_xor_sync(0xffffffffu, v, 2);
      if (kq == 0) red[(w * 8 + bb) * 12 + r] = v;
    }
    __syncthreads();

    if (tid < 128) {
      int bg2 = b_ >> 3, bb2 = b_ & 7;
      int base0 = ((bg2 * 2 + 0) * 8 + bb2) * 12 + jj_ * 3;
      int base1 = ((bg2 * 2 + 1) * 8 + bb2) * 12 + jj_ * 3;
      float sr = red[base0 + 0] + red[base1 + 0];
      float sz = red[base0 + 1] + red[base1 + 1];
      float sn = red[base0 + 2] + red[base1 + 2];
      float rg = sigmoid_f(xr + sr + bh[jj_ * 3 + 0]);
      float zg = sigmoid_f(xz + sz + bh[jj_ * 3 + 1]);
      float ng = tanh_f(xn + rg * (sn + bh[jj_ * 3 + 2]));
      float hnew = ng + zg * (hprev - ng);
      hn[b_ * HID + jcol] = hnew;
      out[((size_t)b_ * SEQT + t) * HID + jcol] = hnew;
    }
    grid_barrier();
  }
}

extern "C" void kernel_launch(void* const* d_in, const int* in_sizes, int n_in,
                              void* d_out, int out_size) {
  (void)in_sizes; (void)n_in; (void)out_size;
  const float* input = (const float*)d_in[0];
  const float* h0    = (const float*)d_in[1];
  const float* wih   = (const float*)d_in[2];
  const float* whh   = (const float*)d_in[3];
  const float* bih   = (const float*)d_in[4];
  const float* bhh   = (const float*)d_in[5];
  float* out = (float*)d_out;

  dim3 gA(G3 / 128, (BATCH * SEQT) / 128);
  gemm_xgates<<<gA, 256>>>(input, wih, bih);
  gru_scan<<<NB, NT>>>(whh, bhh, h0, out);
}